// round 1
// baseline (speedup 1.0000x reference)
#include <cuda_runtime.h>
#include <math.h>

// ---------------- problem constants ----------------
#define BATCH   8
#define CH      96
#define NTOK    3136          // 56*56
#define COUT    192
#define NPOS    (BATCH * NTOK)   // 25088

// attention tiling
#define MQ      112           // query rows per block (3136 = 28*112)
#define NKEY    64            // keys per tile
#define NTILES  49            // 3136/64
#define QS_STRIDE 100
#define KS_STRIDE 100
#define PS_STRIDE 68

// smem sizes (floats)
#define QS_OFF  0
#define KS_OFF  (MQ * QS_STRIDE)                 // 11200
#define PS_OFF  (KS_OFF + NKEY * KS_STRIDE)      // 17600
#define ST_OFF  (PS_OFF + MQ * PS_STRIDE)        // 25216
#define ATTN_SMEM_FLOATS (ST_OFF + 3 * MQ + 16)
#define ATTN_SMEM_BYTES  (ATTN_SMEM_FLOATS * 4)

// conv kernel smem
#define WS_STRIDE 193
#define CS_STRIDE 33
#define CONV_SMEM_FLOATS (COUT * WS_STRIDE + (2*CH) * CS_STRIDE)
#define CONV_SMEM_BYTES  (CONV_SMEM_FLOATS * 4)
#define CONV_POS 32
#define NCONVBLK (NPOS / CONV_POS)   // 784

// ---------------- scratch (no allocation allowed) ----------------
__device__ float g_xj[BATCH * CH * NTOK];       // relu(x - att), [b,c,n] layout
__device__ float g_y [COUT * NPOS];             // conv output, [o, b*N+n]
__device__ float g_p1[NCONVBLK * COUT];         // partial sum(y)
__device__ float g_p2[NCONVBLK * COUT];         // partial sum(y^2)
__device__ float g_scale[COUT];
__device__ float g_shift[COUT];

// =====================================================================
// Kernel 1: flash attention (q=k=v=x tokens) + x_j = relu(x - att)
// grid (28, 8), 128 threads, 2 blocks/SM -> single wave (224 blocks)
// thread grid: ty = tid/8 (0..15), tx = tid%8 (0..7)
// S micro-tile 7x8  (rows i = ii*16+ty, cols j = jj*8+tx)
// O micro-tile 7x12 (rows i = ii*16+ty, cols ch = jj*8+tx)
// =====================================================================
__global__ void __launch_bounds__(128, 2)
attn_kernel(const float* __restrict__ x)
{
    extern __shared__ float sm[];
    float* Qs   = sm + QS_OFF;
    float* Ks   = sm + KS_OFF;
    float* Ps   = sm + PS_OFF;
    float* mrow = sm + ST_OFF;
    float* lrow = mrow + MQ;
    float* arow = lrow + MQ;

    const int tid = threadIdx.x;
    const int ty  = tid >> 3;        // 0..15
    const int tx  = tid & 7;         // 0..7
    const int b   = blockIdx.y;
    const int n0  = blockIdx.x * MQ;
    const float* xb = x + (size_t)b * CH * NTOK;

    // load Q tile 112 x 96 (vectorized over n)
    for (int v = tid; v < (MQ * CH) / 4; v += 128) {
        int c  = v / (MQ / 4);
        int r4 = (v - c * (MQ / 4)) * 4;
        float4 t = *(const float4*)(xb + c * NTOK + n0 + r4);
        Qs[(r4 + 0) * QS_STRIDE + c] = t.x;
        Qs[(r4 + 1) * QS_STRIDE + c] = t.y;
        Qs[(r4 + 2) * QS_STRIDE + c] = t.z;
        Qs[(r4 + 3) * QS_STRIDE + c] = t.w;
    }
    if (tid < MQ) { mrow[tid] = -INFINITY; lrow[tid] = 0.f; }

    float o_acc[7][12];
    #pragma unroll
    for (int i = 0; i < 7; i++)
        #pragma unroll
        for (int j = 0; j < 12; j++) o_acc[i][j] = 0.f;

    __syncthreads();

    for (int t = 0; t < NTILES; t++) {
        // ---- load K tile 64 x 96 ----
        for (int v = tid; v < (NKEY * CH) / 4; v += 128) {
            int c  = v / (NKEY / 4);
            int r4 = (v - c * (NKEY / 4)) * 4;
            float4 tv = *(const float4*)(xb + c * NTOK + t * NKEY + r4);
            Ks[(r4 + 0) * KS_STRIDE + c] = tv.x;
            Ks[(r4 + 1) * KS_STRIDE + c] = tv.y;
            Ks[(r4 + 2) * KS_STRIDE + c] = tv.z;
            Ks[(r4 + 3) * KS_STRIDE + c] = tv.w;
        }
        __syncthreads();

        // ---- S = Q K^T  (112 x 64), micro 7x8 ----
        float s_acc[7][8];
        #pragma unroll
        for (int i = 0; i < 7; i++)
            #pragma unroll
            for (int j = 0; j < 8; j++) s_acc[i][j] = 0.f;

        for (int c = 0; c < CH; c += 4) {
            float4 aa[7], bb[8];
            #pragma unroll
            for (int ii = 0; ii < 7; ii++)
                aa[ii] = *(const float4*)&Qs[(ii * 16 + ty) * QS_STRIDE + c];
            #pragma unroll
            for (int jj = 0; jj < 8; jj++)
                bb[jj] = *(const float4*)&Ks[(jj * 8 + tx) * KS_STRIDE + c];
            #pragma unroll
            for (int ii = 0; ii < 7; ii++) {
                #pragma unroll
                for (int jj = 0; jj < 8; jj++) {
                    s_acc[ii][jj] += aa[ii].x * bb[jj].x;
                    s_acc[ii][jj] += aa[ii].y * bb[jj].y;
                    s_acc[ii][jj] += aa[ii].z * bb[jj].z;
                    s_acc[ii][jj] += aa[ii].w * bb[jj].w;
                }
            }
        }
        #pragma unroll
        for (int ii = 0; ii < 7; ii++)
            #pragma unroll
            for (int jj = 0; jj < 8; jj++)
                Ps[(ii * 16 + ty) * PS_STRIDE + jj * 8 + tx] = s_acc[ii][jj];
        __syncthreads();

        // ---- online softmax, one thread per row ----
        if (tid < MQ) {
            const int r = tid;
            float mo = mrow[r];
            float tm = mo;
            #pragma unroll 8
            for (int j = 0; j < NKEY; j++) tm = fmaxf(tm, Ps[r * PS_STRIDE + j]);
            float al = __expf(mo - tm);
            float sum = 0.f;
            #pragma unroll 8
            for (int j = 0; j < NKEY; j++) {
                float p = __expf(Ps[r * PS_STRIDE + j] - tm);
                Ps[r * PS_STRIDE + j] = p;
                sum += p;
            }
            lrow[r] = lrow[r] * al + sum;
            mrow[r] = tm;
            arow[r] = al;
        }
        __syncthreads();

        // ---- rescale O, then O += P * V (V = K tile) ----
        float alpha_i[7];
        #pragma unroll
        for (int ii = 0; ii < 7; ii++) alpha_i[ii] = arow[ii * 16 + ty];
        #pragma unroll
        for (int ii = 0; ii < 7; ii++)
            #pragma unroll
            for (int jj = 0; jj < 12; jj++) o_acc[ii][jj] *= alpha_i[ii];

        for (int kk = 0; kk < NKEY; kk += 4) {
            float4 av[7];
            #pragma unroll
            for (int ii = 0; ii < 7; ii++)
                av[ii] = *(const float4*)&Ps[(ii * 16 + ty) * PS_STRIDE + kk];
            #pragma unroll
            for (int dk = 0; dk < 4; dk++) {
                float bb[12];
                #pragma unroll
                for (int jj = 0; jj < 12; jj++)
                    bb[jj] = Ks[(kk + dk) * KS_STRIDE + jj * 8 + tx];
                #pragma unroll
                for (int ii = 0; ii < 7; ii++) {
                    float a = (&av[ii].x)[dk];
                    #pragma unroll
                    for (int jj = 0; jj < 12; jj++)
                        o_acc[ii][jj] += a * bb[jj];
                }
            }
        }
        __syncthreads();
    }

    // ---- epilogue: x_j = relu(x - att) ----
    float inv[7];
    #pragma unroll
    for (int ii = 0; ii < 7; ii++) inv[ii] = 1.f / lrow[ii * 16 + ty];
    #pragma unroll
    for (int ii = 0; ii < 7; ii++) {
        const int n = n0 + ii * 16 + ty;
        #pragma unroll
        for (int jj = 0; jj < 12; jj++) {
            const int ch = jj * 8 + tx;
            float xv  = xb[ch * NTOK + n];
            float att = o_acc[ii][jj] * inv[ii];
            g_xj[((size_t)b * CH + ch) * NTOK + n] = fmaxf(xv - att, 0.f);
        }
    }
}

// =====================================================================
// Kernel 2: 1x1 conv y = W [x; x_j] + bias, + per-block channel partial sums
// grid 784, 256 threads. W fully in smem.
// to = tid/8 owns 6 output channels {to*6..}, tp = tid%8 owns 4 positions.
// =====================================================================
__global__ void __launch_bounds__(256, 1)
conv_kernel(const float* __restrict__ x, const float* __restrict__ w,
            const float* __restrict__ bias)
{
    extern __shared__ float sm[];
    float* Ws = sm;                       // 192 x 193
    float* cs = sm + COUT * WS_STRIDE;    // 192 x 33

    const int tid = threadIdx.x;
    for (int i = tid; i < COUT * (2 * CH); i += 256) {
        int o = i / (2 * CH), k = i - o * (2 * CH);
        Ws[o * WS_STRIDE + k] = w[i];
    }

    const int p0 = blockIdx.x * CONV_POS;
    const int b  = p0 / NTOK;
    const int n0 = p0 - b * NTOK;

    for (int i = tid; i < CH * CONV_POS; i += 256) {
        int k = i / CONV_POS, pp = i - k * CONV_POS;
        size_t gi = ((size_t)b * CH + k) * NTOK + n0 + pp;
        cs[k * CS_STRIDE + pp]          = x[gi];
        cs[(k + CH) * CS_STRIDE + pp]   = g_xj[gi];
    }
    __syncthreads();

    const int to = tid >> 3;   // 0..31
    const int tp = tid & 7;    // 0..7

    float acc[6][4];
    #pragma unroll
    for (int j = 0; j < 6; j++)
        #pragma unroll
        for (int q = 0; q < 4; q++) acc[j][q] = 0.f;

    for (int k = 0; k < 2 * CH; k++) {
        float bb[4];
        #pragma unroll
        for (int q = 0; q < 4; q++) bb[q] = cs[k * CS_STRIDE + tp * 4 + q];
        #pragma unroll
        for (int j = 0; j < 6; j++) {
            float a = Ws[(to * 6 + j) * WS_STRIDE + k];
            #pragma unroll
            for (int q = 0; q < 4; q++) acc[j][q] += a * bb[q];
        }
    }

    #pragma unroll
    for (int j = 0; j < 6; j++) {
        const int o = to * 6 + j;
        const float bi = bias[o];
        float a1 = 0.f, a2 = 0.f;
        #pragma unroll
        for (int q = 0; q < 4; q++) {
            float y = acc[j][q] + bi;
            g_y[(size_t)o * NPOS + p0 + tp * 4 + q] = y;
            a1 += y;
            a2 += y * y;
        }
        // reduce over the 8 position-threads (contiguous lanes, width 8)
        #pragma unroll
        for (int d = 4; d > 0; d >>= 1) {
            a1 += __shfl_down_sync(0xffffffffu, a1, d, 8);
            a2 += __shfl_down_sync(0xffffffffu, a2, d, 8);
        }
        if (tp == 0) {
            g_p1[blockIdx.x * COUT + o] = a1;
            g_p2[blockIdx.x * COUT + o] = a2;
        }
    }
}

// =====================================================================
// Kernel 2b: reduce partials -> per-channel scale/shift (fold BN + gamma/beta)
// grid 192, 256 threads (deterministic reduction, no atomics)
// =====================================================================
__global__ void __launch_bounds__(256)
stats_kernel(const float* __restrict__ gamma, const float* __restrict__ beta)
{
    const int o = blockIdx.x;
    const int tid = threadIdx.x;
    float s1 = 0.f, s2 = 0.f;
    for (int i = tid; i < NCONVBLK; i += 256) {
        s1 += g_p1[i * COUT + o];
        s2 += g_p2[i * COUT + o];
    }
    __shared__ float r1[256], r2[256];
    r1[tid] = s1; r2[tid] = s2;
    __syncthreads();
    for (int d = 128; d > 0; d >>= 1) {
        if (tid < d) { r1[tid] += r1[tid + d]; r2[tid] += r2[tid + d]; }
        __syncthreads();
    }
    if (tid == 0) {
        const float invN = 1.f / (float)NPOS;
        float mean = r1[0] * invN;
        float var  = r2[0] * invN - mean * mean;
        float rstd = rsqrtf(var + 1e-5f);
        float g = gamma[o] * rstd;
        g_scale[o] = g;
        g_shift[o] = beta[o] - mean * g;
    }
}

// =====================================================================
// Kernel 3: BN apply + exact GELU, layout [o, p] -> out [b, o, n]
// total 4816896 elems, float4 per thread, grid 4704 x 256
// =====================================================================
__global__ void __launch_bounds__(256)
bngelu_kernel(float* __restrict__ out)
{
    const int idx4 = blockIdx.x * 256 + threadIdx.x;
    const int base = idx4 * 4;
    const int o = base / NPOS;
    const int p = base - o * NPOS;
    const int b = p / NTOK;
    const int n = p - b * NTOK;

    float4 v = *(const float4*)(g_y + base);
    const float sc = g_scale[o], sh = g_shift[o];
    float r[4] = {v.x, v.y, v.z, v.w};
    #pragma unroll
    for (int i = 0; i < 4; i++) {
        float u = r[i] * sc + sh;
        r[i] = 0.5f * u * (1.f + erff(u * 0.70710678118654752f));
    }
    float4 ov = {r[0], r[1], r[2], r[3]};
    *(float4*)(out + (size_t)b * (COUT * NTOK) + (size_t)o * NTOK + n) = ov;
}

// =====================================================================
extern "C" void kernel_launch(void* const* d_in, const int* in_sizes, int n_in,
                              void* d_out, int out_size)
{
    const float* x     = (const float*)d_in[0];
    const float* w     = (const float*)d_in[1];
    const float* bias  = (const float*)d_in[2];
    const float* gamma = (const float*)d_in[3];
    const float* beta  = (const float*)d_in[4];
    float* out = (float*)d_out;

    cudaFuncSetAttribute(attn_kernel, cudaFuncAttributeMaxDynamicSharedMemorySize, ATTN_SMEM_BYTES);
    cudaFuncSetAttribute(conv_kernel, cudaFuncAttributeMaxDynamicSharedMemorySize, CONV_SMEM_BYTES);

    attn_kernel<<<dim3(NTOK / MQ, BATCH), 128, ATTN_SMEM_BYTES>>>(x);
    conv_kernel<<<NCONVBLK, 256, CONV_SMEM_BYTES>>>(x, w, bias);
    stats_kernel<<<COUT, 256>>>(gamma, beta);
    bngelu_kernel<<<(COUT * NPOS) / 4 / 256, 256>>>(out);
}